// round 16
// baseline (speedup 1.0000x reference)
#include <cuda_runtime.h>
#include <cuda_bf16.h>
#include <math.h>
#include <stdint.h>
#include <string.h>

// ---------------- problem constants ----------------
#define NB   16
#define SEQ  1025
#define NP   1024
#define ND   768
#define NFP  64
#define KR   8
#define KSPARSE 307          // max(1, int(1024*0.3))
#define NEGV (-1000000000.0f)

// ---------------- device scratch ----------------
__device__ float g_q[NB * NP * ND];
__device__ float g_k[NB * NP * ND];
__device__ float g_v[NB * NP * ND];
__device__ float g_scores[NB * NP * NP];
__device__ float g_routed[NB * NP * ND];
__device__ int   g_routes[NB * NP * KR];
__device__ float g_weights[NB * NP * KR];
__device__ float g_cn[NP];
__device__ float g_thr[NP];
__device__ float g_gate[ND];

// affinity — identical in thresh and mask epilogue
__device__ __forceinline__ float aff_of(float cni, float cnj)
{
    return __fsub_rn(1.0f, fabsf(__fsub_rn(cni, cnj)));
}

// ---------------- XLA f32 tanh rational approximation (STRICT) ----------------
__device__ __forceinline__ float tanh_xla(float x)
{
    if (fabsf(x) < 0.0004f) return x;
    const float kClamp = 7.90531110763549805f;
    float xc = fmaxf(-kClamp, fminf(kClamp, x));
    float x2 = __fmul_rn(xc, xc);
    float p = -2.76076847742355e-16f;
    p = __fadd_rn(__fmul_rn(p, x2),  2.00018790482477e-13f);
    p = __fadd_rn(__fmul_rn(p, x2), -8.60467152213735e-11f);
    p = __fadd_rn(__fmul_rn(p, x2),  5.12229709037114e-08f);
    p = __fadd_rn(__fmul_rn(p, x2),  1.48572235717979e-05f);
    p = __fadd_rn(__fmul_rn(p, x2),  6.37261928875436e-04f);
    p = __fadd_rn(__fmul_rn(p, x2),  4.89352455891786e-03f);
    float num = __fmul_rn(xc, p);
    float q = 1.19825839466702e-06f;
    q = __fadd_rn(__fmul_rn(q, x2), 1.18534705686654e-04f);
    q = __fadd_rn(__fmul_rn(q, x2), 2.26843463243900e-03f);
    q = __fadd_rn(__fmul_rn(q, x2), 4.89352518554385e-03f);
    return __fdiv_rn(num, q);
}

// ---------------- Cephes/Eigen pexp f32 (XLA vectorized exp), fma form ----------------
__device__ __forceinline__ float pexp_fma(float x)
{
    x = fmaxf(fminf(x, 88.3762626647950f), -87.3365478515625f);
    float m = floorf(fmaf(x, 1.44269504088896341f, 0.5f));
    float r = fmaf(m, -0.693359375f, x);
    r = fmaf(m, 2.12194440e-4f, r);
    float r2 = __fmul_rn(r, r);
    float y = 1.9875691500E-4f;
    y = fmaf(y, r, 1.3981999507E-3f);
    y = fmaf(y, r, 8.3334519073E-3f);
    y = fmaf(y, r, 4.1665795894E-2f);
    y = fmaf(y, r, 1.6666665459E-1f);
    y = fmaf(y, r, 5.0000001201E-1f);
    y = fmaf(y, r2, r);
    y = __fadd_rn(y, 1.0f);
    int mi = (int)m;
    uint32_t bits = (uint32_t)(127 + mi) << 23;
    float s; memcpy(&s, &bits, 4);
    return __fmul_rn(y, s);
}

// logistic = 1/(1+exp(-x)), exp = XLA vector exp (E2-class sigma)
__device__ __forceinline__ float sigmoid_pexp(float x)
{
    float e   = pexp_fma(-x);
    float den = __fadd_rn(1.0f, e);
    return __fdiv_rn(1.0f, den);
}

// ---------------- cantor cn ----------------
__global__ void cantor_kernel(const float* __restrict__ fp,
                              const float* __restrict__ W_off,
                              const float* __restrict__ b_off)
{
    __shared__ float s_scale, s_shift;
    __shared__ float red[32];
    __shared__ float sinv;
    int t = threadIdx.x;  // 1024 threads
    if (t == 0) {
        // strict sequential rn mul + rn add, bias after (route-neutral order)
        float d0 = 0.0f, d1 = 0.0f;
        for (int f = 0; f < NFP; f++) {
            d0 = __fadd_rn(d0, __fmul_rn(W_off[0 * NFP + f], fp[f]));
            d1 = __fadd_rn(d1, __fmul_rn(W_off[1 * NFP + f], fp[f]));
        }
        float p0 = __fadd_rn(d0, b_off[0]);
        float p1 = __fadd_rn(d1, b_off[1]);
        float sig = sigmoid_pexp(p0);
        s_scale = __fadd_rn(__fmul_rn(sig, 2.0f), 0.5f);
        s_shift = __fmul_rn(tanh_xla(p1), 32.0f);
    }
    __syncthreads();
    int gx = t & 31, gy = t >> 5;
    int zz = ((gx + gy) * (gx + gy + 1)) / 2 + gy;
    float z = (float)zz;                                    // exact
    float c = __fadd_rn(__fmul_rn(z, s_scale), s_shift);    // strict c (E2 base)

    float m = c;
    for (int o = 16; o; o >>= 1) m = fmaxf(m, __shfl_xor_sync(0xffffffffu, m, o));
    if ((t & 31) == 0) red[t >> 5] = m;
    __syncthreads();
    if (t < 32) {
        float mm = red[t];
        for (int o = 16; o; o >>= 1) mm = fmaxf(mm, __shfl_xor_sync(0xffffffffu, mm, o));
        if (t == 0) {
            float den = fmaxf(mm, 1.0f);
            // PROBE (unevaluated in R15 due to infra): hoisted reciprocal
            // (LLVM arcp fast-math), cn = c * rn(1/den) instead of rn(c/den)
            sinv = __fdiv_rn(1.0f, den);
        }
    }
    __syncthreads();
    g_cn[t] = __fmul_rn(c, sinv);
}

// per-row exact 307th-largest affinity via bitonic sort
__global__ void thresh_kernel()
{
    __shared__ float v[NP];
    int row = blockIdx.x;
    int i = threadIdx.x;  // 1024
    float cni = g_cn[row];
    v[i] = (i == row) ? NEGV : aff_of(cni, g_cn[i]);
    __syncthreads();
    for (int k = 2; k <= NP; k <<= 1) {
        for (int j = k >> 1; j > 0; j >>= 1) {
            int l = i ^ j;
            if (l > i) {
                float vi = v[i], vl = v[l];
                bool up = ((i & k) == 0);
                if ((vi > vl) == up) { v[i] = vl; v[l] = vi; }
            }
            __syncthreads();
        }
    }
    if (i == 0) g_thr[row] = v[NP - KSPARSE];
}

__global__ void gate_kernel(const float* __restrict__ fp,
                            const float* __restrict__ Wg,
                            const float* __restrict__ bg)
{
    int d = threadIdx.x;  // 768
    if (d < ND) {
        float s = 0.0f;
        for (int f = 0; f < NFP; f++)
            s = __fadd_rn(s, __fmul_rn(Wg[d * NFP + f], fp[f]));
        s = __fadd_rn(s, bg[d]);
        g_gate[d] = sigmoid_pexp(s);
    }
}

// normalize rows: exact sumsq (double), single rounding, rn fp32 chain.
__global__ void normalize_rows(float* __restrict__ a)
{
    int row = blockIdx.x;
    float* r = a + (size_t)row * ND;
    int t = threadIdx.x;  // 256
    float v0 = r[t], v1 = r[t + 256], v2 = r[t + 512];
    double ss = (double)v0 * (double)v0
              + (double)v1 * (double)v1
              + (double)v2 * (double)v2;
    for (int o = 16; o; o >>= 1) ss += __shfl_xor_sync(0xffffffffu, ss, o);
    __shared__ double sw[8];
    __shared__ float sden;
    if ((t & 31) == 0) sw[t >> 5] = ss;
    __syncthreads();
    if (t == 0) {
        double tot = 0.0;
        for (int i = 0; i < 8; i++) tot += sw[i];
        float sf = (float)tot;
        float nrm = sqrtf(sf);
        sden = fmaxf(nrm, 1e-12f);
    }
    __syncthreads();
    float d = sden;
    r[t]       = __fdiv_rn(v0, d);
    r[t + 256] = __fdiv_rn(v1, d);
    r[t + 512] = __fdiv_rn(v2, d);
}

// ---------------- fp32 tiled GEMM: C = A(MxK) @ B(NxK)^T ----------------
#define BM 128
#define BN 64
#define BKT 16

template<int EPI, bool REMAP>
__global__ void __launch_bounds__(256)
sgemm_tn(const float* __restrict__ A,
         const float* __restrict__ Bm,
         float* __restrict__ C,
         int M, int N, int K,
         long strideA, long strideB, long strideC,
         const float* __restrict__ bias,
         const float* __restrict__ xres)
{
    __shared__ float As[BKT][BM + 4];
    __shared__ float Bs[BKT][BN + 4];
    int z = blockIdx.z;
    const float* Ab = REMAP ? A : (A + (size_t)z * strideA);
    const float* Bb = Bm + (size_t)z * strideB;
    int m0 = blockIdx.y * BM;
    int n0 = blockIdx.x * BN;
    int tid = threadIdx.x;          // 256
    int ak = (tid & 3) * 4;
    int ar = tid >> 2;              // 0..63
    int ty = tid >> 4;              // 0..15 -> 8 rows
    int tx = tid & 15;              // 0..15 -> 4 cols

    float acc[8][4];
#pragma unroll
    for (int i = 0; i < 8; i++)
#pragma unroll
        for (int j = 0; j < 4; j++) acc[i][j] = 0.0f;

    for (int k0 = 0; k0 < K; k0 += BKT) {
#pragma unroll
        for (int h = 0; h < 2; h++) {
            int m = m0 + ar + h * 64;
            long gr = m;
            if (REMAP) gr = (long)m + (m >> 10) + 1;  // skip cls row per batch
            float4 a4 = *(const float4*)&Ab[gr * (long)K + k0 + ak];
            As[ak + 0][ar + h * 64] = a4.x;
            As[ak + 1][ar + h * 64] = a4.y;
            As[ak + 2][ar + h * 64] = a4.z;
            As[ak + 3][ar + h * 64] = a4.w;
        }
        {
            int n = n0 + ar;
            float4 b4 = *(const float4*)&Bb[(long)n * K + k0 + ak];
            Bs[ak + 0][ar] = b4.x;
            Bs[ak + 1][ar] = b4.y;
            Bs[ak + 2][ar] = b4.z;
            Bs[ak + 3][ar] = b4.w;
        }
        __syncthreads();
#pragma unroll
        for (int kk = 0; kk < BKT; kk++) {   // ascending k, serial FMA chain
            float aR[8], bR[4];
            *(float4*)&aR[0] = *(const float4*)&As[kk][ty * 8];
            *(float4*)&aR[4] = *(const float4*)&As[kk][ty * 8 + 4];
            *(float4*)&bR[0] = *(const float4*)&Bs[kk][tx * 4];
#pragma unroll
            for (int i = 0; i < 8; i++)
#pragma unroll
                for (int j = 0; j < 4; j++) acc[i][j] = fmaf(aR[i], bR[j], acc[i][j]);
        }
        __syncthreads();
    }

#pragma unroll
    for (int i = 0; i < 8; i++) {
        int m = m0 + ty * 8 + i;
#pragma unroll
        for (int j = 0; j < 4; j++) {
            int n = n0 + tx * 4 + j;
            float val = acc[i][j];
            if (EPI == 0) {
                C[(size_t)m * N + n] = __fadd_rn(val, bias[n]);
            } else if (EPI == 1) {
                C[(size_t)m * N + n] = __fmul_rn(__fadd_rn(val, bias[n]), g_gate[n]);
            } else if (EPI == 2) {
                float aff = aff_of(g_cn[m], g_cn[n]);
                bool allowed = (aff >= g_thr[m]) && (m != n);
                C[(size_t)z * strideC + (size_t)m * N + n] = allowed ? val : NEGV;
            } else {
                size_t gr = ((size_t)z * SEQ + 1 + m) * (size_t)ND + n;
                C[gr] = val + bias[n] + xres[gr];
            }
        }
    }
}

// ---------------- top-8 + softmax ----------------
__device__ __forceinline__ void insert8(float* v, int* ix, float nv, int ni)
{
#pragma unroll
    for (int s = 0; s < 8; s++) {
        if (nv > v[s]) {
#pragma unroll
            for (int q = 7; q > s; q--) { v[q] = v[q - 1]; ix[q] = ix[q - 1]; }
            v[s] = nv; ix[s] = ni;
            return;
        }
    }
}

__device__ __forceinline__ void merge8(float* av, int* ai,
                                       const float* bv, const int* bi)
{
    float rv[8]; int ri[8];
    int pa = 0, pb = 0;
#pragma unroll
    for (int r = 0; r < 8; r++) {
        float va = av[pa < 8 ? pa : 7]; int ia = ai[pa < 8 ? pa : 7];
        float vb = bv[pb < 8 ? pb : 7]; int ib = bi[pb < 8 ? pb : 7];
        bool ta;
        if (pa >= 8) ta = false;
        else if (pb >= 8) ta = true;
        else ta = (va > vb) || (va == vb && ia < ib);   // stable: lower index first
        rv[r] = ta ? va : vb;
        ri[r] = ta ? ia : ib;
        if (ta) pa++; else pb++;
    }
#pragma unroll
    for (int r = 0; r < 8; r++) { av[r] = rv[r]; ai[r] = ri[r]; }
}

__global__ void topk_kernel(float* __restrict__ out_routes_f,
                            float* __restrict__ out_weights,
                            int*   __restrict__ out_routes_i)
{
    int p = blockIdx.x, b = blockIdx.y;
    const float* row = g_scores + ((size_t)b * NP + p) * NP;
    int t = threadIdx.x;  // 128 threads, 8 cols each
    float tv[8]; int ti_[8];
#pragma unroll
    for (int j = 0; j < 8; j++) { tv[j] = -3.0e38f; ti_[j] = 0x7fffffff; }
    int c0 = t * 8;
#pragma unroll
    for (int j = 0; j < 8; j++) {
        int c = c0 + j;
        float s = __fdiv_rn(row[c], 0.1f);
        insert8(tv, ti_, s, c);
    }
#pragma unroll
    for (int off = 16; off; off >>= 1) {
        float ov[8]; int oi[8];
#pragma unroll
        for (int j = 0; j < 8; j++) {
            ov[j] = __shfl_down_sync(0xffffffffu, tv[j], off);
            oi[j] = __shfl_down_sync(0xffffffffu, ti_[j], off);
        }
        merge8(tv, ti_, ov, oi);
    }
    __shared__ float sv[4][8];
    __shared__ int   si[4][8];
    int lane = t & 31, w = t >> 5;
    if (lane == 0) {
#pragma unroll
        for (int j = 0; j < 8; j++) { sv[w][j] = tv[j]; si[w][j] = ti_[j]; }
    }
    __syncthreads();
    if (t == 0) {
        for (int ww = 1; ww < 4; ww++) merge8(tv, ti_, sv[ww], si[ww]);
        float m = tv[0];
        float e[8], s = 0.0f;
#pragma unroll
        for (int k = 0; k < 8; k++) { e[k] = expf(tv[k] - m); s += e[k]; }
        size_t base = ((size_t)b * NP + p) * KR;
#pragma unroll
        for (int k = 0; k < 8; k++) {
            float wk = e[k] / s;
            g_routes[base + k]  = ti_[k];
            g_weights[base + k] = wk;
            if (out_routes_f) out_routes_f[base + k] = (float)ti_[k];
            if (out_weights)  out_weights[base + k]  = wk;
            if (out_routes_i) out_routes_i[base + k] = ti_[k];
        }
    }
}

// routed[b,p,:] = sum_k w_k * v[b, route_k, :]
__global__ void gather_kernel()
{
    int p = blockIdx.x, b = blockIdx.y;
    __shared__ float w[8]; __shared__ int r[8];
    int t = threadIdx.x;  // 192 threads, float4 each
    size_t base = ((size_t)b * NP + p) * KR;
    if (t < 8) { w[t] = g_weights[base + t]; r[t] = g_routes[base + t]; }
    __syncthreads();
    const float* vb = g_v + (size_t)b * NP * ND;
    float* ob = g_routed + ((size_t)b * NP + p) * ND;
    int d = t * 4;
    if (d < ND) {
        float4 acc = make_float4(0.f, 0.f, 0.f, 0.f);
#pragma unroll
        for (int k = 0; k < 8; k++) {
            float4 vv = *(const float4*)&vb[(size_t)r[k] * ND + d];
            float wk = w[k];
            acc.x = fmaf(wk, vv.x, acc.x);
            acc.y = fmaf(wk, vv.y, acc.y);
            acc.z = fmaf(wk, vv.z, acc.z);
            acc.w = fmaf(wk, vv.w, acc.w);
        }
        *(float4*)&ob[d] = acc;
    }
}

__global__ void cls_copy_kernel(const float* __restrict__ x, float* __restrict__ out_x)
{
    int b = blockIdx.x;
    int d = threadIdx.x;  // 768
    size_t idx = (size_t)b * SEQ * ND + d;
    out_x[idx] = x[idx];
}

// ---------------- launcher ----------------
extern "C" void kernel_launch(void* const* d_in, const int* in_sizes, int n_in,
                              void* d_out, int out_size)
{
    const float* x     = (const float*)d_in[0];
    const float* fp    = (const float*)d_in[1];
    const float* Wq    = (const float*)d_in[2];
    const float* bq    = (const float*)d_in[3];
    const float* Wk    = (const float*)d_in[4];
    const float* bk    = (const float*)d_in[5];
    const float* Wv    = (const float*)d_in[6];
    const float* bv    = (const float*)d_in[7];
    const float* Wo    = (const float*)d_in[8];
    const float* bo    = (const float*)d_in[9];
    const float* Wg    = (const float*)d_in[10];
    const float* bg    = (const float*)d_in[11];
    const float* W_off = (const float*)d_in[12];
    const float* b_off = (const float*)d_in[13];

    float *pq, *pk, *pv, *pscores, *prouted;
    cudaGetSymbolAddress((void**)&pq, g_q);
    cudaGetSymbolAddress((void**)&pk, g_k);
    cudaGetSymbolAddress((void**)&pv, g_v);
    cudaGetSymbolAddress((void**)&pscores, g_scores);
    cudaGetSymbolAddress((void**)&prouted, g_routed);

    const long RW = (long)NB * NP * KR;   // 131072

    cantor_kernel<<<1, 1024>>>(fp, W_off, b_off);
    thresh_kernel<<<NP, 1024>>>();

    dim3 gproj(ND / BN, (NB * NP) / BM, 1);
    sgemm_tn<0, true><<<gproj, 256>>>(x, Wq, pq, NB * NP, ND, ND, 0, 0, 0, bq, nullptr);
    sgemm_tn<0, true><<<gproj, 256>>>(x, Wk, pk, NB * NP, ND, ND, 0, 0, 0, bk, nullptr);

    normalize_rows<<<NB * NP, 256>>>(pq);
    normalize_rows<<<NB * NP, 256>>>(pk);

    dim3 gsc(NP / BN, NP / BM, NB);
    sgemm_tn<2, false><<<gsc, 256>>>(pq, pk, pscores, NP, NP, ND,
                                     (long)NP * ND, (long)NP * ND, (long)NP * NP,
                                     nullptr, nullptr);

    if ((long)out_size == RW) {
        topk_kernel<<<dim3(NP, NB), 128>>>(nullptr, nullptr, (int*)d_out);
        return;
    }

    float* out = (float*)d_out;
    float* out_routes  = out;
    float* out_weights = out + RW;
    float* out_x       = out + 2 * RW;

    gate_kernel<<<1, ND>>>(fp, Wg, bg);
    sgemm_tn<1, true><<<gproj, 256>>>(x, Wv, pv, NB * NP, ND, ND, 0, 0, 0, bv, nullptr);

    topk_kernel<<<dim3(NP, NB), 128>>>(out_routes, out_weights, nullptr);
    gather_kernel<<<dim3(NP, NB), 192>>>();

    dim3 gout(ND / BN, NP / BM, NB);
    sgemm_tn<3, false><<<gout, 256>>>(prouted, Wo, out_x, NP, ND, ND,
                                      (long)NP * ND, 0, 0, bo, x);

    cls_copy_kernel<<<NB, ND>>>(x, out_x);
}